// round 3
// baseline (speedup 1.0000x reference)
#include <cuda_runtime.h>

// Problem constants
#define B_ 16
#define C_ 64
#define T_ 64
#define N_ 512

// Scratch: intermediate M = W1@x + 2*W2@Z1   [B, c_out, T, N] (128 MB)
__device__ float g_M[(size_t)B_ * C_ * T_ * N_];
// Folded weights: [o][0:64]=W1, [o][64:128]=2*W2, [o][128:192]=W0-W2
__device__ float g_Wmix[C_ * 192];

typedef unsigned long long u64;

__device__ __forceinline__ u64 pack2(float x, float y) {
    u64 r;
    asm("mov.b64 %0, {%1, %2};" : "=l"(r) : "f"(x), "f"(y));
    return r;
}
__device__ __forceinline__ void fma2(u64 &d, u64 a, u64 b) {
    // packed fp32x2 FMA (sm_103a): d.lo += a.lo*b.lo; d.hi += a.hi*b.hi
    asm("fma.rn.f32x2 %0, %1, %2, %0;" : "+l"(d) : "l"(a), "l"(b));
}
__device__ __forceinline__ void unpack2(u64 v, float &x, float &y) {
    asm("mov.b64 {%0, %1}, %2;" : "=f"(x), "=f"(y) : "l"(v));
}

// ---------------------------------------------------------------------------
// K0: build folded weight table
// ---------------------------------------------------------------------------
__global__ void k_wmix(const float* __restrict__ W) {
    int i = blockIdx.x * blockDim.x + threadIdx.x;
    if (i >= C_ * 192) return;
    int o = i / 192;
    int r = i - o * 192;
    float v;
    if (r < 64)       v = W[o * 192 + 3 * r + 1];                                   // W1
    else if (r < 128) v = 2.0f * W[o * 192 + 3 * (r - 64) + 2];                     // 2*W2
    else              v = W[o * 192 + 3 * (r - 128)] - W[o * 192 + 3 * (r - 128) + 2]; // W0-W2
    g_Wmix[i] = v;
}

// ---------------------------------------------------------------------------
// Shared GEMM core: acc[row][colpair] += As[row][n] * La[q][n]  (k-dim n = 512)
//   As: [64][512] in smem.  Bt: 32x256 staging in smem.
//   Thread (tr,tc): rows tr*8..tr*8+7, column pairs {2tc,2tc+1}+64j (j=0..3).
//   Lab: per-thread pointer to La row (q0 + tid).
// ---------------------------------------------------------------------------
__device__ __forceinline__ void gemm_core(const float* __restrict__ As,
                                          float* __restrict__ Bt,
                                          const float* __restrict__ Lab,
                                          u64 acc[8][4], int tr, int tc, int tid) {
    #pragma unroll 1
    for (int n0 = 0; n0 < N_; n0 += 32) {
        // Stage Bt[nn][q] = La[q0+q][n0+nn]  (thread tid owns row q=tid)
        const float4* Lr = (const float4*)(Lab + n0);
        #pragma unroll
        for (int v = 0; v < 8; v++) {
            float4 f = __ldg(&Lr[v]);
            Bt[(v * 4 + 0) * 256 + tid] = f.x;
            Bt[(v * 4 + 1) * 256 + tid] = f.y;
            Bt[(v * 4 + 2) * 256 + tid] = f.z;
            Bt[(v * 4 + 3) * 256 + tid] = f.w;
        }
        __syncthreads();
        #pragma unroll 1
        for (int nn4 = 0; nn4 < 32; nn4 += 4) {
            float4 a4[8];
            #pragma unroll
            for (int ii = 0; ii < 8; ii++)
                a4[ii] = *(const float4*)&As[(tr * 8 + ii) * N_ + n0 + nn4];
            #pragma unroll
            for (int s = 0; s < 4; s++) {
                u64 bv[4];
                #pragma unroll
                for (int j = 0; j < 4; j++)
                    bv[j] = *(const u64*)&Bt[(nn4 + s) * 256 + (tc << 1) + (j << 6)];
                #pragma unroll
                for (int ii = 0; ii < 8; ii++) {
                    float a = (s == 0) ? a4[ii].x : (s == 1) ? a4[ii].y
                            : (s == 2) ? a4[ii].z : a4[ii].w;
                    u64 ap = pack2(a, a);
                    #pragma unroll
                    for (int j = 0; j < 4; j++) fma2(acc[ii][j], ap, bv[j]);
                }
            }
        }
        __syncthreads();
    }
}

// ---------------------------------------------------------------------------
// K1: per (b, t, q-half):
//   Z1[c,q] = sum_n x[b,c,t,n] * La[b,q,n]
//   M [o,q] = sum_c W1[o,c]*x[b,c,t,q] + 2*sum_c W2[o,c]*Z1[c,q]   -> g_M
//   A0[o,q] = sum_c (W0-W2)[o,c]*x[b,c,t,q]                        -> d_out
// smem: Xs 64x512 (128KB) + U (union: Bt 32x256 / Z1s 64x256, 64KB) = 192KB
// ---------------------------------------------------------------------------
__global__ __launch_bounds__(256, 1)
void k_cheb1(const float* __restrict__ x, const float* __restrict__ La,
             float* __restrict__ out) {
    extern __shared__ float sm[];
    float* Xs = sm;               // [64][512]
    float* U  = sm + C_ * N_;     // Bt during GEMM, Z1s after

    int tid = threadIdx.x;
    int blk = blockIdx.x;
    int b  = blk >> 7;
    int t  = (blk >> 1) & 63;
    int q0 = (blk & 1) << 8;
    int tr = tid >> 5, tc = tid & 31;

    // Load x[b, :, t, :] -> Xs[c][n]
    for (int i = tid; i < C_ * (N_ / 4); i += 256) {
        int c = i >> 7;
        int v = i & 127;
        float4 f = __ldg((const float4*)x +
                         (((size_t)((b * C_ + c) * T_ + t) * N_) >> 2) + v);
        *(float4*)&Xs[c * N_ + v * 4] = f;
    }
    __syncthreads();

    u64 acc[8][4];
    #pragma unroll
    for (int ii = 0; ii < 8; ii++)
        #pragma unroll
        for (int j = 0; j < 4; j++) acc[ii][j] = 0ull;

    const float* Lab = La + (size_t)(b * N_ + q0 + tid) * N_;
    gemm_core(Xs, U, Lab, acc, tr, tc, tid);   // acc = Z1 tile (rows=c)

    // Stash Z1 into U (Bt no longer needed; gemm_core ends with a sync)
    #pragma unroll
    for (int ii = 0; ii < 8; ii++)
        #pragma unroll
        for (int j = 0; j < 4; j++)
            *(u64*)&U[(tr * 8 + ii) * 256 + (tc << 1) + (j << 6)] = acc[ii][j];
    __syncthreads();

    // Channel-mix epilogue (rows become o). Weights via L1-cached LDG broadcast.
    u64 accM[8][4], accA[8][4];
    #pragma unroll
    for (int ii = 0; ii < 8; ii++)
        #pragma unroll
        for (int j = 0; j < 4; j++) { accM[ii][j] = 0ull; accA[ii][j] = 0ull; }

    #pragma unroll 2
    for (int r = 0; r < 64; r++) {         // phase A: terms from X
        u64 bx[4];
        #pragma unroll
        for (int j = 0; j < 4; j++)
            bx[j] = *(const u64*)&Xs[r * N_ + q0 + (tc << 1) + (j << 6)];
        #pragma unroll
        for (int ii = 0; ii < 8; ii++) {
            int o = tr * 8 + ii;
            float w1 = __ldg(&g_Wmix[o * 192 + r]);
            float w0 = __ldg(&g_Wmix[o * 192 + 128 + r]);
            u64 p1 = pack2(w1, w1), p0 = pack2(w0, w0);
            #pragma unroll
            for (int j = 0; j < 4; j++) {
                fma2(accM[ii][j], p1, bx[j]);
                fma2(accA[ii][j], p0, bx[j]);
            }
        }
    }
    #pragma unroll 2
    for (int r = 0; r < 64; r++) {         // phase B: terms from Z1
        u64 bz[4];
        #pragma unroll
        for (int j = 0; j < 4; j++)
            bz[j] = *(const u64*)&U[r * 256 + (tc << 1) + (j << 6)];
        #pragma unroll
        for (int ii = 0; ii < 8; ii++) {
            float w2 = __ldg(&g_Wmix[(tr * 8 + ii) * 192 + 64 + r]);
            u64 p2 = pack2(w2, w2);
            #pragma unroll
            for (int j = 0; j < 4; j++) fma2(accM[ii][j], p2, bz[j]);
        }
    }

    #pragma unroll
    for (int ii = 0; ii < 8; ii++) {
        int o = tr * 8 + ii;
        size_t base = (size_t)((b * C_ + o) * T_ + t) * N_ + q0;
        #pragma unroll
        for (int j = 0; j < 4; j++) {
            int col = (tc << 1) + (j << 6);
            *(u64*)&g_M[base + col] = accM[ii][j];
            *(u64*)&out[base + col] = accA[ii][j];   // A0
        }
    }
}

// ---------------------------------------------------------------------------
// K2: per (b, o, q-half): out[b,o,t,q] += sum_n M[b,o,t,n] * La[b,q,n]
// smem: Ms 64x512 (128KB) + Bt 32x256 (32KB) = 160KB
// ---------------------------------------------------------------------------
__global__ __launch_bounds__(256, 1)
void k_cheb2(const float* __restrict__ La, float* __restrict__ out) {
    extern __shared__ float sm[];
    float* Ms = sm;
    float* Bt = sm + C_ * N_;

    int tid = threadIdx.x;
    int blk = blockIdx.x;
    int b  = blk >> 7;
    int o  = (blk >> 1) & 63;
    int q0 = (blk & 1) << 8;
    int tr = tid >> 5, tc = tid & 31;

    const float* Msrc = g_M + (size_t)(b * C_ + o) * T_ * N_;   // [t][n] contiguous
    for (int i = tid; i < T_ * N_ / 4; i += 256)
        *(float4*)&Ms[i * 4] = __ldg((const float4*)Msrc + i);
    __syncthreads();

    u64 acc[8][4];
    #pragma unroll
    for (int ii = 0; ii < 8; ii++)
        #pragma unroll
        for (int j = 0; j < 4; j++) acc[ii][j] = 0ull;

    const float* Lab = La + (size_t)(b * N_ + q0 + tid) * N_;
    gemm_core(Ms, Bt, Lab, acc, tr, tc, tid);   // rows = t

    #pragma unroll
    for (int ii = 0; ii < 8; ii++) {
        int t = tr * 8 + ii;
        size_t base = (size_t)((b * C_ + o) * T_ + t) * N_ + q0;
        #pragma unroll
        for (int j = 0; j < 4; j++) {
            int col = (tc << 1) + (j << 6);
            float lo, hi;
            unpack2(acc[ii][j], lo, hi);
            float2 p = *(float2*)&out[base + col];   // A0 written by K1
            p.x += lo; p.y += hi;
            *(float2*)&out[base + col] = p;
        }
    }
}

// ---------------------------------------------------------------------------
extern "C" void kernel_launch(void* const* d_in, const int* in_sizes, int n_in,
                              void* d_out, int out_size) {
    const float* x  = (const float*)d_in[0];
    const float* La = (const float*)d_in[1];
    const float* W  = (const float*)d_in[2];
    float* out = (float*)d_out;

    (void)in_sizes; (void)n_in; (void)out_size;

    cudaFuncSetAttribute(k_cheb1, cudaFuncAttributeMaxDynamicSharedMemorySize, 196608);
    cudaFuncSetAttribute(k_cheb2, cudaFuncAttributeMaxDynamicSharedMemorySize, 163840);

    k_wmix<<<48, 256>>>(W);
    k_cheb1<<<B_ * T_ * 2, 256, 196608>>>(x, La, out);   // 2048 blocks
    k_cheb2<<<B_ * C_ * 2, 256, 163840>>>(La, out);      // 2048 blocks
}

// round 4
// speedup vs baseline: 1.0026x; 1.0026x over previous
#include <cuda_runtime.h>

// Problem constants
#define B_ 16
#define C_ 64
#define T_ 64
#define N_ 512

// Scratch: intermediate M = W1@x + 2*W2@Z1   [B, c_out, T, N] (128 MB)
__device__ float g_M[(size_t)B_ * C_ * T_ * N_];
// Folded weights: [o][0:64]=W1, [o][64:128]=2*W2, [o][128:192]=W0-W2
__device__ float g_Wmix[C_ * 192];

typedef unsigned long long u64;

__device__ __forceinline__ u64 pack2(float x, float y) {
    u64 r;
    asm("mov.b64 %0, {%1, %2};" : "=l"(r) : "f"(x), "f"(y));
    return r;
}
__device__ __forceinline__ void fma2(u64 &d, u64 a, u64 b) {
    // packed fp32x2 FMA (sm_103a): d.lo += a.lo*b.lo; d.hi += a.hi*b.hi
    asm("fma.rn.f32x2 %0, %1, %2, %0;" : "+l"(d) : "l"(a), "l"(b));
}
__device__ __forceinline__ void unpack2(u64 v, float &x, float &y) {
    asm("mov.b64 {%0, %1}, %2;" : "=f"(x), "=f"(y) : "l"(v));
}

// ---------------------------------------------------------------------------
// K0: build folded weight table
// ---------------------------------------------------------------------------
__global__ void k_wmix(const float* __restrict__ W) {
    int i = blockIdx.x * blockDim.x + threadIdx.x;
    if (i >= C_ * 192) return;
    int o = i / 192;
    int r = i - o * 192;
    float v;
    if (r < 64)       v = W[o * 192 + 3 * r + 1];                                   // W1
    else if (r < 128) v = 2.0f * W[o * 192 + 3 * (r - 64) + 2];                     // 2*W2
    else              v = W[o * 192 + 3 * (r - 128)] - W[o * 192 + 3 * (r - 128) + 2]; // W0-W2
    g_Wmix[i] = v;
}

// ---------------------------------------------------------------------------
// Shared GEMM core: acc[row][colpair] += As[row][n] * La[q][n]  (k-dim n = 512)
//   As: [64][512] in smem.  Bt: 32x256 staging in smem.
//   Thread (tr,tc): rows tr*8..tr*8+7, column pairs {2tc,2tc+1}+64j (j=0..3).
//   Lab: per-thread pointer to La row (q0 + tid).
// ---------------------------------------------------------------------------
__device__ __forceinline__ void gemm_core(const float* __restrict__ As,
                                          float* __restrict__ Bt,
                                          const float* __restrict__ Lab,
                                          u64 acc[8][4], int tr, int tc, int tid) {
    #pragma unroll 1
    for (int n0 = 0; n0 < N_; n0 += 32) {
        // Stage Bt[nn][q] = La[q0+q][n0+nn]  (thread tid owns row q=tid)
        const float4* Lr = (const float4*)(Lab + n0);
        #pragma unroll
        for (int v = 0; v < 8; v++) {
            float4 f = __ldg(&Lr[v]);
            Bt[(v * 4 + 0) * 256 + tid] = f.x;
            Bt[(v * 4 + 1) * 256 + tid] = f.y;
            Bt[(v * 4 + 2) * 256 + tid] = f.z;
            Bt[(v * 4 + 3) * 256 + tid] = f.w;
        }
        __syncthreads();
        #pragma unroll 1
        for (int nn4 = 0; nn4 < 32; nn4 += 4) {
            float4 a4[8];
            #pragma unroll
            for (int ii = 0; ii < 8; ii++)
                a4[ii] = *(const float4*)&As[(tr * 8 + ii) * N_ + n0 + nn4];
            #pragma unroll
            for (int s = 0; s < 4; s++) {
                u64 bv[4];
                #pragma unroll
                for (int j = 0; j < 4; j++)
                    bv[j] = *(const u64*)&Bt[(nn4 + s) * 256 + (tc << 1) + (j << 6)];
                #pragma unroll
                for (int ii = 0; ii < 8; ii++) {
                    float a = (s == 0) ? a4[ii].x : (s == 1) ? a4[ii].y
                            : (s == 2) ? a4[ii].z : a4[ii].w;
                    u64 ap = pack2(a, a);
                    #pragma unroll
                    for (int j = 0; j < 4; j++) fma2(acc[ii][j], ap, bv[j]);
                }
            }
        }
        __syncthreads();
    }
}

// ---------------------------------------------------------------------------
// K1: per (b, t, q-half):
//   Z1[c,q] = sum_n x[b,c,t,n] * La[b,q,n]
//   M [o,q] = sum_c W1[o,c]*x[b,c,t,q] + 2*sum_c W2[o,c]*Z1[c,q]   -> g_M
//   A0[o,q] = sum_c (W0-W2)[o,c]*x[b,c,t,q]                        -> d_out
// smem: Xs 64x512 (128KB) + U (union: Bt 32x256 / Z1s 64x256, 64KB) = 192KB
// ---------------------------------------------------------------------------
__global__ __launch_bounds__(256, 1)
void k_cheb1(const float* __restrict__ x, const float* __restrict__ La,
             float* __restrict__ out) {
    extern __shared__ float sm[];
    float* Xs = sm;               // [64][512]
    float* U  = sm + C_ * N_;     // Bt during GEMM, Z1s after

    int tid = threadIdx.x;
    int blk = blockIdx.x;
    int b  = blk >> 7;
    int t  = (blk >> 1) & 63;
    int q0 = (blk & 1) << 8;
    int tr = tid >> 5, tc = tid & 31;

    // Load x[b, :, t, :] -> Xs[c][n]
    for (int i = tid; i < C_ * (N_ / 4); i += 256) {
        int c = i >> 7;
        int v = i & 127;
        float4 f = __ldg((const float4*)x +
                         (((size_t)((b * C_ + c) * T_ + t) * N_) >> 2) + v);
        *(float4*)&Xs[c * N_ + v * 4] = f;
    }
    __syncthreads();

    u64 acc[8][4];
    #pragma unroll
    for (int ii = 0; ii < 8; ii++)
        #pragma unroll
        for (int j = 0; j < 4; j++) acc[ii][j] = 0ull;

    const float* Lab = La + (size_t)(b * N_ + q0 + tid) * N_;
    gemm_core(Xs, U, Lab, acc, tr, tc, tid);   // acc = Z1 tile (rows=c)

    // Stash Z1 into U (Bt no longer needed; gemm_core ends with a sync)
    #pragma unroll
    for (int ii = 0; ii < 8; ii++)
        #pragma unroll
        for (int j = 0; j < 4; j++)
            *(u64*)&U[(tr * 8 + ii) * 256 + (tc << 1) + (j << 6)] = acc[ii][j];
    __syncthreads();

    // Channel-mix epilogue (rows become o). Weights via L1-cached LDG broadcast.
    u64 accM[8][4], accA[8][4];
    #pragma unroll
    for (int ii = 0; ii < 8; ii++)
        #pragma unroll
        for (int j = 0; j < 4; j++) { accM[ii][j] = 0ull; accA[ii][j] = 0ull; }

    #pragma unroll 2
    for (int r = 0; r < 64; r++) {         // phase A: terms from X
        u64 bx[4];
        #pragma unroll
        for (int j = 0; j < 4; j++)
            bx[j] = *(const u64*)&Xs[r * N_ + q0 + (tc << 1) + (j << 6)];
        #pragma unroll
        for (int ii = 0; ii < 8; ii++) {
            int o = tr * 8 + ii;
            float w1 = __ldg(&g_Wmix[o * 192 + r]);
            float w0 = __ldg(&g_Wmix[o * 192 + 128 + r]);
            u64 p1 = pack2(w1, w1), p0 = pack2(w0, w0);
            #pragma unroll
            for (int j = 0; j < 4; j++) {
                fma2(accM[ii][j], p1, bx[j]);
                fma2(accA[ii][j], p0, bx[j]);
            }
        }
    }
    #pragma unroll 2
    for (int r = 0; r < 64; r++) {         // phase B: terms from Z1
        u64 bz[4];
        #pragma unroll
        for (int j = 0; j < 4; j++)
            bz[j] = *(const u64*)&U[r * 256 + (tc << 1) + (j << 6)];
        #pragma unroll
        for (int ii = 0; ii < 8; ii++) {
            float w2 = __ldg(&g_Wmix[(tr * 8 + ii) * 192 + 64 + r]);
            u64 p2 = pack2(w2, w2);
            #pragma unroll
            for (int j = 0; j < 4; j++) fma2(accM[ii][j], p2, bz[j]);
        }
    }

    #pragma unroll
    for (int ii = 0; ii < 8; ii++) {
        int o = tr * 8 + ii;
        size_t base = (size_t)((b * C_ + o) * T_ + t) * N_ + q0;
        #pragma unroll
        for (int j = 0; j < 4; j++) {
            int col = (tc << 1) + (j << 6);
            *(u64*)&g_M[base + col] = accM[ii][j];
            *(u64*)&out[base + col] = accA[ii][j];   // A0
        }
    }
}

// ---------------------------------------------------------------------------
// K2: per (b, o, q-half): out[b,o,t,q] += sum_n M[b,o,t,n] * La[b,q,n]
// smem: Ms 64x512 (128KB) + Bt 32x256 (32KB) = 160KB
// ---------------------------------------------------------------------------
__global__ __launch_bounds__(256, 1)
void k_cheb2(const float* __restrict__ La, float* __restrict__ out) {
    extern __shared__ float sm[];
    float* Ms = sm;
    float* Bt = sm + C_ * N_;

    int tid = threadIdx.x;
    int blk = blockIdx.x;
    int b  = blk >> 7;
    int o  = (blk >> 1) & 63;
    int q0 = (blk & 1) << 8;
    int tr = tid >> 5, tc = tid & 31;

    const float* Msrc = g_M + (size_t)(b * C_ + o) * T_ * N_;   // [t][n] contiguous
    for (int i = tid; i < T_ * N_ / 4; i += 256)
        *(float4*)&Ms[i * 4] = __ldg((const float4*)Msrc + i);
    __syncthreads();

    u64 acc[8][4];
    #pragma unroll
    for (int ii = 0; ii < 8; ii++)
        #pragma unroll
        for (int j = 0; j < 4; j++) acc[ii][j] = 0ull;

    const float* Lab = La + (size_t)(b * N_ + q0 + tid) * N_;
    gemm_core(Ms, Bt, Lab, acc, tr, tc, tid);   // rows = t

    #pragma unroll
    for (int ii = 0; ii < 8; ii++) {
        int t = tr * 8 + ii;
        size_t base = (size_t)((b * C_ + o) * T_ + t) * N_ + q0;
        #pragma unroll
        for (int j = 0; j < 4; j++) {
            int col = (tc << 1) + (j << 6);
            float lo, hi;
            unpack2(acc[ii][j], lo, hi);
            float2 p = *(float2*)&out[base + col];   // A0 written by K1
            p.x += lo; p.y += hi;
            *(float2*)&out[base + col] = p;
        }
    }
}

// ---------------------------------------------------------------------------
extern "C" void kernel_launch(void* const* d_in, const int* in_sizes, int n_in,
                              void* d_out, int out_size) {
    const float* x  = (const float*)d_in[0];
    const float* La = (const float*)d_in[1];
    const float* W  = (const float*)d_in[2];
    float* out = (float*)d_out;

    (void)in_sizes; (void)n_in; (void)out_size;

    cudaFuncSetAttribute(k_cheb1, cudaFuncAttributeMaxDynamicSharedMemorySize, 196608);
    cudaFuncSetAttribute(k_cheb2, cudaFuncAttributeMaxDynamicSharedMemorySize, 163840);

    k_wmix<<<48, 256>>>(W);
    k_cheb1<<<B_ * T_ * 2, 256, 196608>>>(x, La, out);   // 2048 blocks
    k_cheb2<<<B_ * C_ * 2, 256, 163840>>>(La, out);      // 2048 blocks
}

// round 9
// speedup vs baseline: 2.4482x; 2.4418x over previous
#include <cuda_runtime.h>
#include <cuda_bf16.h>
#include <cstdint>

// Shapes: x[16,64,64,512], La[16,512,512], W[64,192]; out[16,64,64,512]
#define BELEM 2097152            // 64*64*512 elements per batch (row=o*64+t, col=n)
#define LAELEM 262144            // 512*512

typedef unsigned short u16;
typedef unsigned int u32;

__device__ __align__(16) float g_U1[(size_t)16 * BELEM];          // 128 MB fp32
__device__ __align__(16) u16   g_U2h[(size_t)16 * BELEM];         // 64 MB
__device__ __align__(16) u16   g_U2l[(size_t)16 * BELEM];
__device__ __align__(16) u16   g_Ph [(size_t)16 * BELEM];
__device__ __align__(16) u16   g_Pl [(size_t)16 * BELEM];
__device__ __align__(16) u16   g_Lah[(size_t)16 * LAELEM];        // 8 MB
__device__ __align__(16) u16   g_Lal[(size_t)16 * LAELEM];
__device__ __align__(16) u16   g_Wsh[192 * 64];
__device__ __align__(16) u16   g_Wsl[192 * 64];

// ---------------------------------------------------------------------------
__device__ __forceinline__ u32 s2u(const void* p) {
    u32 a;
    asm("{ .reg .u64 t; cvta.to.shared.u64 t, %1; cvt.u32.u64 %0, t; }" : "=r"(a) : "l"(p));
    return a;
}
// 128B-row swizzle: rows of 64 bf16; 16B chunk c XORed by row&7 -> conflict-free
__device__ __forceinline__ u32 swz(int row, int kb) {
    return (u32)(row * 128 + (kb ^ ((row & 7) << 4)));
}
__device__ __forceinline__ void cpa(u32 s, const void* g) {
    asm volatile("cp.async.cg.shared.global [%0], [%1], 16;" :: "r"(s), "l"(g));
}
__device__ __forceinline__ void cpcommit() {
    asm volatile("cp.async.commit_group;" ::: "memory");
}
template<int N> __device__ __forceinline__ void cpwait() {
    asm volatile("cp.async.wait_group %0;" :: "n"(N) : "memory");
}
__device__ __forceinline__ void ldsm4(u32* r, u32 a) {
    asm volatile("ldmatrix.sync.aligned.m8n8.x4.shared.b16 {%0,%1,%2,%3}, [%4];"
        : "=r"(r[0]), "=r"(r[1]), "=r"(r[2]), "=r"(r[3]) : "r"(a));
}
__device__ __forceinline__ void mma_bf(float* d, const u32* a, u32 b0, u32 b1) {
    asm volatile("mma.sync.aligned.m16n8k16.row.col.f32.bf16.bf16.f32 "
        "{%0,%1,%2,%3}, {%4,%5,%6,%7}, {%8,%9}, {%0,%1,%2,%3};"
        : "+f"(d[0]), "+f"(d[1]), "+f"(d[2]), "+f"(d[3])
        : "r"(a[0]), "r"(a[1]), "r"(a[2]), "r"(a[3]), "r"(b0), "r"(b1));
}
__device__ __forceinline__ u32 packlo(float lx, float ly) {   // {ly|hi, lx|lo}
    u32 r;
    asm("cvt.rn.bf16x2.f32 %0, %1, %2;" : "=r"(r) : "f"(ly), "f"(lx));
    return r;
}
// hi = exact truncation (top 16 bits), lo = RN(v - hi); packed bf16x2 pairs
__device__ __forceinline__ void store_hl(u16* H, u16* L, size_t off, float v0, float v1) {
    u32 b0 = __float_as_uint(v0), b1 = __float_as_uint(v1);
    *(u32*)(H + off) = __byte_perm(b0, b1, 0x7632);
    float r0 = v0 - __uint_as_float(b0 & 0xFFFF0000u);
    float r1 = v1 - __uint_as_float(b1 & 0xFFFF0000u);
    *(u32*)(L + off) = packlo(r0, r1);
}

// ---------------------------------------------------------------------------
// k_prep: La fp32 -> bf16 hi/lo
// ---------------------------------------------------------------------------
__global__ void k_prep(const float* __restrict__ La) {
    int i = blockIdx.x * blockDim.x + threadIdx.x;   // float4 index, 1048576 total
    float4 v = __ldg((const float4*)La + i);
    u32 bx = __float_as_uint(v.x), by = __float_as_uint(v.y);
    u32 bz = __float_as_uint(v.z), bw = __float_as_uint(v.w);
    uint2 h = { __byte_perm(bx, by, 0x7632), __byte_perm(bz, bw, 0x7632) };
    uint2 l = { packlo(v.x - __uint_as_float(bx & 0xFFFF0000u),
                       v.y - __uint_as_float(by & 0xFFFF0000u)),
                packlo(v.z - __uint_as_float(bz & 0xFFFF0000u),
                       v.w - __uint_as_float(bw & 0xFFFF0000u)) };
    ((uint2*)g_Lah)[i] = h;
    ((uint2*)g_Lal)[i] = l;
}

// ---------------------------------------------------------------------------
// k_wstk: folded weights -> bf16 hi/lo. A rows: 0-63 W1, 64-127 2*W2, 128-191 W0-W2
// ---------------------------------------------------------------------------
__global__ void k_wstk(const float* __restrict__ W) {
    int i = blockIdx.x * blockDim.x + threadIdx.x;
    if (i >= 192 * 64) return;
    int r = i >> 6, c = i & 63;
    int o = r & 63, reg = r >> 6;
    float v = (reg == 0) ? W[o * 192 + 3 * c + 1]
            : (reg == 1) ? 2.0f * W[o * 192 + 3 * c + 2]
            : W[o * 192 + 3 * c] - W[o * 192 + 3 * c + 2];
    u32 u = __float_as_uint(v);
    g_Wsh[i] = (u16)(u >> 16);
    float res = v - __uint_as_float(u & 0xFFFF0000u);
    __nv_bfloat16 rb = __float2bfloat16(res);
    g_Wsl[i] = *(u16*)&rb;
}

// ---------------------------------------------------------------------------
// k_mix: per (b,t): A=Wstk[192][64] h/l, B=X^T chunks [128 n][64 c] h/l.
// Rows 0-63 -> U1 (fp32), 64-127 -> U2 (h/l), 128-191 -> out (fp32).
// smem: Wh 0 (24K), Wl 24576, Bh 49152 (16K), Bl 65536, stage 81920 (32K fp32)
// ---------------------------------------------------------------------------
__global__ __launch_bounds__(256, 1)
void k_mix(const float* __restrict__ x, float* __restrict__ out) {
    extern __shared__ char sm[];
    int tid = threadIdx.x, w = tid >> 5, l = tid & 31;
    int b = blockIdx.x >> 6, t = blockIdx.x & 63;
    u32 su = s2u(sm);
    float* stage = (float*)(sm + 81920);

    // load W tiles (3072 16B chunks)
    #pragma unroll
    for (int it = 0; it < 12; it++) {
        int idx = it * 256 + tid;
        int half = idx >= 1536;
        int rem = idx - half * 1536;
        int r = rem >> 3, c = rem & 7;
        const u16* g = (half ? g_Wsl : g_Wsh) + r * 64 + c * 8;
        cpa(su + half * 24576 + swz(r, c * 16), g);
    }
    cpcommit();

    const float* xb = x + (size_t)b * BELEM + (size_t)t * 512;  // + c*32768 + n
    int wm = (w >> 1) * 48, wn = (w & 1) * 64;
    int rA = ((l >> 3) & 1) * 8 + (l & 7);
    int ksel = ((l >> 4) & 1) * 16;

    for (int nc = 0; nc < 4; nc++) {
        int n0 = nc * 128;
        #pragma unroll
        for (int it = 0; it < 8; it++) {          // stage X[64 c][128 n] fp32
            int idx = it * 256 + tid;
            int c = idx >> 5, q = idx & 31;
            cpa(su + 81920 + (u32)(c * 512 + q * 16), xb + (size_t)c * 32768 + n0 + q * 4);
        }
        cpcommit();
        cpwait<0>();
        __syncthreads();
        #pragma unroll
        for (int it = 0; it < 16; it++) {         // transpose+convert -> Bh/Bl [n][c]
            int idx = it * 256 + tid;
            int cp2 = idx >> 7, n = idx & 127;
            float a0 = stage[(cp2 * 2) * 128 + n];
            float a1 = stage[(cp2 * 2 + 1) * 128 + n];
            u32 u0 = __float_as_uint(a0), u1 = __float_as_uint(a1);
            u32 off = swz(n, cp2 * 4);
            *(u32*)(sm + 49152 + off) = __byte_perm(u0, u1, 0x7632);
            *(u32*)(sm + 65536 + off) = packlo(a0 - __uint_as_float(u0 & 0xFFFF0000u),
                                               a1 - __uint_as_float(u1 & 0xFFFF0000u));
        }
        __syncthreads();

        float acc[3][8][4];
        #pragma unroll
        for (int mi = 0; mi < 3; mi++)
            #pragma unroll
            for (int ni = 0; ni < 8; ni++)
                #pragma unroll
                for (int j = 0; j < 4; j++) acc[mi][ni][j] = 0.0f;

        #pragma unroll
        for (int s = 0; s < 4; s++) {
            int kb = s * 32 + ksel;
            u32 ah[3][4], al[3][4], bh[4][4], bl[4][4];
            #pragma unroll
            for (int mi = 0; mi < 3; mi++) {
                ldsm4(ah[mi], su + swz(wm + mi * 16 + rA, kb));
                ldsm4(al[mi], su + 24576 + swz(wm + mi * 16 + rA, kb));
            }
            #pragma unroll
            for (int g4 = 0; g4 < 4; g4++) {
                ldsm4(bh[g4], su + 49152 + swz(wn + g4 * 16 + rA, kb));
                ldsm4(bl[g4], su + 65536 + swz(wn + g4 * 16 + rA, kb));
            }
            #pragma unroll
            for (int mi = 0; mi < 3; mi++)
                #pragma unroll
                for (int ni = 0; ni < 8; ni++) {
                    int g4 = ni >> 1, o = ni & 1;
                    mma_bf(acc[mi][ni], ah[mi], bh[g4][o], bh[g4][o + 2]);
                    mma_bf(acc[mi][ni], al[mi], bh[g4][o], bh[g4][o + 2]);
                    mma_bf(acc[mi][ni], ah[mi], bl[g4][o], bl[g4][o + 2]);
                }
        }

        // epilogue
        #pragma unroll
        for (int mi = 0; mi < 3; mi++) {
            int mb = wm + mi * 16;
            int reg = mb >> 6;
            int o = (mb & 63) + (l >> 2);
            size_t base = (size_t)b * BELEM + (size_t)o * 32768 + (size_t)t * 512;
            #pragma unroll
            for (int ni = 0; ni < 8; ni++) {
                int col = n0 + wn + ni * 8 + 2 * (l & 3);
                float* d = acc[mi][ni];
                size_t o0 = base + col, o1 = o0 + (size_t)8 * 32768;
                if (reg == 0) {
                    float2 v0 = { d[0], d[1] }, v1 = { d[2], d[3] };
                    *(float2*)&g_U1[o0] = v0;
                    *(float2*)&g_U1[o1] = v1;
                } else if (reg == 1) {
                    store_hl(g_U2h, g_U2l, o0, d[0], d[1]);
                    store_hl(g_U2h, g_U2l, o1, d[2], d[3]);
                } else {
                    float2 v0 = { d[0], d[1] }, v1 = { d[2], d[3] };
                    *(float2*)&out[o0] = v0;
                    *(float2*)&out[o1] = v1;
                }
            }
        }
        __syncthreads();
    }
}

// ---------------------------------------------------------------------------
// k_gemm: pass0: P = U1 + U2@La^T (-> Ph/Pl); pass1: out = out + P@La^T.
// CTA 128x128, K=512 in 8 chunks of 64, double-buffered cp.async.
// buffer layout (per 64KB buf): Ah 0, Al 16384, Bh 32768, Bl 49152
// ---------------------------------------------------------------------------
__device__ __forceinline__ void load_chunk(u32 sb, const u16* A0, const u16* A1,
                                           const u16* B0, const u16* B1,
                                           int kc, int tid) {
    int k0 = kc * 64;
    #pragma unroll
    for (int it = 0; it < 16; it++) {
        int idx = it * 256 + tid;
        int tile = idx >> 10;
        int r = (idx >> 3) & 127, c = idx & 7;
        const u16* g = (tile == 0 ? A0 : tile == 1 ? A1 : tile == 2 ? B0 : B1)
                     + (size_t)r * 512 + k0 + c * 8;
        cpa(sb + tile * 16384 + swz(r, c * 16), g);
    }
    cpcommit();
}

__global__ __launch_bounds__(256, 1)
void k_gemm(float* __restrict__ out, int pass) {
    extern __shared__ char sm[];
    int tid = threadIdx.x, w = tid >> 5, l = tid & 31;
    int blk = blockIdx.x;
    int b = blk >> 7, mt = (blk >> 2) & 31, qt = blk & 3;
    int m0 = mt * 128, q0 = qt * 128;

    const u16* A0 = (pass ? g_Ph : g_U2h) + (size_t)b * BELEM + (size_t)m0 * 512;
    const u16* A1 = (pass ? g_Pl : g_U2l) + (size_t)b * BELEM + (size_t)m0 * 512;
    const u16* B0 = g_Lah + (size_t)b * LAELEM + (size_t)q0 * 512;
    const u16* B1 = g_Lal + (size_t)b * LAELEM + (size_t)q0 * 512;
    u32 su = s2u(sm);

    load_chunk(su, A0, A1, B0, B1, 0, tid);

    float acc[2][8][4];
    #pragma unroll
    for (int mi = 0; mi < 2; mi++)
        #pragma unroll
        for (int ni = 0; ni < 8; ni++)
            #pragma unroll
            for (int j = 0; j < 4; j++) acc[mi][ni][j] = 0.0f;

    int wm = (w >> 1) * 32, wn = (w & 1) * 64;
    int rA = ((l >> 3) & 1) * 8 + (l & 7);
    int ksel = ((l >> 4) & 1) * 16;

    for (int kc = 0; kc < 8; kc++) {
        if (kc < 7) {
            load_chunk(su + ((kc + 1) & 1) * 65536, A0, A1, B0, B1, kc + 1, tid);
            cpwait<1>();
        } else {
            cpwait<0>();
        }
        __syncthreads();
        u32 sb = su + (kc & 1) * 65536;
        #pragma unroll
        for (int s = 0; s < 4; s++) {
            int kb = s * 32 + ksel;
            u32 ah[2][4], al[2][4], bh[4][4], bl[4][4];
            #pragma unroll
            for (int mi = 0; mi < 2; mi++) {
                ldsm4(ah[mi], sb + swz(wm + mi * 16 + rA, kb));
                ldsm4(al[mi], sb + 16384 + swz(wm + mi * 16 + rA, kb));
            }
            #pragma unroll
            for (int g4 = 0; g4 < 4; g4++) {
                ldsm4(bh[g4], sb + 32768 + swz(wn + g4 * 16 + rA, kb));
                ldsm4(bl[g4], sb + 49152 + swz(wn + g4 * 16 + rA, kb));
            }
            #pragma unroll
            for (int mi = 0; mi < 2; mi++)
                #pragma unroll
                for (int ni = 0; ni < 8; ni++) {
                    int g4 = ni >> 1, o = ni & 1;
                    mma_bf(acc[mi][ni], ah[mi], bh[g4][o], bh[g4][o + 2]);
                    mma_bf(acc[mi][ni], al[mi], bh[g4][o], bh[g4][o + 2]);
                    mma_bf(acc[mi][ni], ah[mi], bl[g4][o], bl[g4][o + 2]);
                }
        }
        __syncthreads();
    }

    // epilogue
    #pragma unroll
    for (int mi = 0; mi < 2; mi++)
        #pragma unroll
        for (int ni = 0; ni < 8; ni++) {
            int row = m0 + wm + mi * 16 + (l >> 2);
            int col = q0 + wn + ni * 8 + 2 * (l & 3);
            size_t o0 = (size_t)b * BELEM + (size_t)row * 512 + col;
            size_t o1 = o0 + 8 * 512;
            float* d = acc[mi][ni];
            if (pass == 0) {
                float2 c0 = *(const float2*)&g_U1[o0];
                float2 c1 = *(const float2*)&g_U1[o1];
                store_hl(g_Ph, g_Pl, o0, d[0] + c0.x, d[1] + c0.y);
                store_hl(g_Ph, g_Pl, o1, d[2] + c1.x, d[3] + c1.y);
            } else {
                float2 c0 = *(const float2*)&out[o0];
                float2 c1 = *(const float2*)&out[o1];
                float2 v0 = { d[0] + c0.x, d[1] + c0.y };
                float2 v1 = { d[2] + c1.x, d[3] + c1.y };
                *(float2*)&out[o0] = v0;
                *(float2*)&out[o1] = v1;
            }
        }
}

// ---------------------------------------------------------------------------
extern "C" void kernel_launch(void* const* d_in, const int* in_sizes, int n_in,
                              void* d_out, int out_size) {
    const float* x  = (const float*)d_in[0];
    const float* La = (const float*)d_in[1];
    const float* W  = (const float*)d_in[2];
    float* out = (float*)d_out;
    (void)in_sizes; (void)n_in; (void)out_size;

    cudaFuncSetAttribute(k_mix,  cudaFuncAttributeMaxDynamicSharedMemorySize, 114688);
    cudaFuncSetAttribute(k_gemm, cudaFuncAttributeMaxDynamicSharedMemorySize, 131072);

    k_prep<<<4096, 256>>>(La);
    k_wstk<<<48, 256>>>(W);
    k_mix<<<1024, 256, 114688>>>(x, out);
    k_gemm<<<2048, 256, 131072>>>(out, 0);
    k_gemm<<<2048, 256, 131072>>>(out, 1);
}

// round 11
// speedup vs baseline: 2.5451x; 1.0396x over previous
#include <cuda_runtime.h>
#include <cuda_bf16.h>
#include <cstdint>

// Shapes: x[16,64,64,512], La[16,512,512], W[64,192]; out[16,64,64,512]
#define BELEM 2097152            // 64*64*512 per batch (row=o*64+t, col=n)
#define LAELEM 262144            // 512*512

typedef unsigned short u16;
typedef unsigned int u32;

__device__ __align__(16) float g_U1[(size_t)16 * BELEM];
__device__ __align__(16) u16   g_U2h[(size_t)16 * BELEM];
__device__ __align__(16) u16   g_U2l[(size_t)16 * BELEM];
__device__ __align__(16) u16   g_Ph [(size_t)16 * BELEM];
__device__ __align__(16) u16   g_Pl [(size_t)16 * BELEM];
__device__ __align__(16) u16   g_Lah[(size_t)16 * LAELEM];
__device__ __align__(16) u16   g_Lal[(size_t)16 * LAELEM];
__device__ __align__(16) u16   g_Wsh[192 * 64];
__device__ __align__(16) u16   g_Wsl[192 * 64];

// ---------------------------------------------------------------------------
__device__ __forceinline__ u32 s2u(const void* p) {
    u32 a;
    asm("{ .reg .u64 t; cvta.to.shared.u64 t, %1; cvt.u32.u64 %0, t; }" : "=r"(a) : "l"(p));
    return a;
}
__device__ __forceinline__ u32 swz(int row, int kb) {
    return (u32)(row * 128 + (kb ^ ((row & 7) << 4)));
}
__device__ __forceinline__ void cpa(u32 s, const void* g) {
    asm volatile("cp.async.cg.shared.global [%0], [%1], 16;" :: "r"(s), "l"(g));
}
__device__ __forceinline__ void cpcommit() {
    asm volatile("cp.async.commit_group;" ::: "memory");
}
template<int N> __device__ __forceinline__ void cpwait() {
    asm volatile("cp.async.wait_group %0;" :: "n"(N) : "memory");
}
__device__ __forceinline__ void ldsm4(u32* r, u32 a) {
    asm volatile("ldmatrix.sync.aligned.m8n8.x4.shared.b16 {%0,%1,%2,%3}, [%4];"
        : "=r"(r[0]), "=r"(r[1]), "=r"(r[2]), "=r"(r[3]) : "r"(a));
}
__device__ __forceinline__ void mma_bf(float* d, const u32* a, u32 b0, u32 b1) {
    asm volatile("mma.sync.aligned.m16n8k16.row.col.f32.bf16.bf16.f32 "
        "{%0,%1,%2,%3}, {%4,%5,%6,%7}, {%8,%9}, {%0,%1,%2,%3};"
        : "+f"(d[0]), "+f"(d[1]), "+f"(d[2]), "+f"(d[3])
        : "r"(a[0]), "r"(a[1]), "r"(a[2]), "r"(a[3]), "r"(b0), "r"(b1));
}
__device__ __forceinline__ u32 packlo(float lx, float ly) {
    u32 r;
    asm("cvt.rn.bf16x2.f32 %0, %1, %2;" : "=r"(r) : "f"(ly), "f"(lx));
    return r;
}
__device__ __forceinline__ void store_hl(u16* H, u16* L, size_t off, float v0, float v1) {
    u32 b0 = __float_as_uint(v0), b1 = __float_as_uint(v1);
    *(u32*)(H + off) = __byte_perm(b0, b1, 0x7632);
    float r0 = v0 - __uint_as_float(b0 & 0xFFFF0000u);
    float r1 = v1 - __uint_as_float(b1 & 0xFFFF0000u);
    *(u32*)(L + off) = packlo(r0, r1);
}

// ---------------------------------------------------------------------------
__global__ void k_prep(const float* __restrict__ La) {
    int i = blockIdx.x * blockDim.x + threadIdx.x;
    float4 v = __ldg((const float4*)La + i);
    u32 bx = __float_as_uint(v.x), by = __float_as_uint(v.y);
    u32 bz = __float_as_uint(v.z), bw = __float_as_uint(v.w);
    uint2 h = { __byte_perm(bx, by, 0x7632), __byte_perm(bz, bw, 0x7632) };
    uint2 l = { packlo(v.x - __uint_as_float(bx & 0xFFFF0000u),
                       v.y - __uint_as_float(by & 0xFFFF0000u)),
                packlo(v.z - __uint_as_float(bz & 0xFFFF0000u),
                       v.w - __uint_as_float(bw & 0xFFFF0000u)) };
    ((uint2*)g_Lah)[i] = h;
    ((uint2*)g_Lal)[i] = l;
}

__global__ void k_wstk(const float* __restrict__ W) {
    int i = blockIdx.x * blockDim.x + threadIdx.x;
    if (i >= 192 * 64) return;
    int r = i >> 6, c = i & 63;
    int o = r & 63, reg = r >> 6;
    float v = (reg == 0) ? W[o * 192 + 3 * c + 1]
            : (reg == 1) ? 2.0f * W[o * 192 + 3 * c + 2]
            : W[o * 192 + 3 * c] - W[o * 192 + 3 * c + 2];
    u32 u = __float_as_uint(v);
    g_Wsh[i] = (u16)(u >> 16);
    float res = v - __uint_as_float(u & 0xFFFF0000u);
    __nv_bfloat16 rb = __float2bfloat16(res);
    g_Wsl[i] = *(u16*)&rb;
}

// ---------------------------------------------------------------------------
// k_mix (512 thr): per (b,t): A=Wstk[192][64] h/l, B=X^T [128 n][64 c] h/l.
// Rows 0-63 -> U1 fp32, 64-127 -> U2 h/l, 128-191 -> out fp32.
// smem: Wh 0 (24K), Wl 24576, Bh 49152 (16K), Bl 65536, stage 81920 (32K fp32)
// warps: 16 = 4 m-warps (48 rows) x 4 n-warps (32 cols)
// ---------------------------------------------------------------------------
__global__ __launch_bounds__(512, 1)
void k_mix(const float* __restrict__ x, float* __restrict__ out) {
    extern __shared__ char sm[];
    int tid = threadIdx.x, w = tid >> 5, l = tid & 31;
    int b = blockIdx.x >> 6, t = blockIdx.x & 63;
    u32 su = s2u(sm);
    float* stage = (float*)(sm + 81920);

    #pragma unroll
    for (int it = 0; it < 6; it++) {               // W: 3072 16B chunks
        int idx = it * 512 + tid;
        int half = idx >= 1536;
        int rem = idx - half * 1536;
        int r = rem >> 3, c = rem & 7;
        const u16* g = (half ? g_Wsl : g_Wsh) + r * 64 + c * 8;
        cpa(su + half * 24576 + swz(r, c * 16), g);
    }
    cpcommit();

    const float* xb = x + (size_t)b * BELEM + (size_t)t * 512;
    int wm = (w >> 2) * 48, wn = (w & 3) * 32;
    int rA = ((l >> 3) & 1) * 8 + (l & 7);
    int ksel = ((l >> 4) & 1) * 16;

    for (int nc = 0; nc < 4; nc++) {
        int n0 = nc * 128;
        #pragma unroll
        for (int it = 0; it < 4; it++) {           // stage X[64 c][128 n] fp32
            int idx = it * 512 + tid;
            int c = idx >> 5, q = idx & 31;
            cpa(su + 81920 + (u32)(c * 512 + q * 16), xb + (size_t)c * 32768 + n0 + q * 4);
        }
        cpcommit();
        cpwait<0>();
        __syncthreads();
        #pragma unroll
        for (int it = 0; it < 8; it++) {           // transpose+convert -> B [n][c]
            int idx = it * 512 + tid;
            int cp2 = idx >> 7, n = idx & 127;
            float a0 = stage[(cp2 * 2) * 128 + n];
            float a1 = stage[(cp2 * 2 + 1) * 128 + n];
            u32 u0 = __float_as_uint(a0), u1 = __float_as_uint(a1);
            u32 off = swz(n, cp2 * 4);
            *(u32*)(sm + 49152 + off) = __byte_perm(u0, u1, 0x7632);
            *(u32*)(sm + 65536 + off) = packlo(a0 - __uint_as_float(u0 & 0xFFFF0000u),
                                               a1 - __uint_as_float(u1 & 0xFFFF0000u));
        }
        __syncthreads();

        float acc[3][4][4];
        #pragma unroll
        for (int mi = 0; mi < 3; mi++)
            #pragma unroll
            for (int ni = 0; ni < 4; ni++)
                #pragma unroll
                for (int j = 0; j < 4; j++) acc[mi][ni][j] = 0.0f;

        #pragma unroll
        for (int s = 0; s < 4; s++) {
            int kb = s * 32 + ksel;
            u32 ah[3][4], al[3][4];
            #pragma unroll
            for (int mi = 0; mi < 3; mi++) {
                ldsm4(ah[mi], su + swz(wm + mi * 16 + rA, kb));
                ldsm4(al[mi], su + 24576 + swz(wm + mi * 16 + rA, kb));
            }
            #pragma unroll
            for (int g4 = 0; g4 < 2; g4++) {
                u32 bh[4], bl[4];
                ldsm4(bh, su + 49152 + swz(wn + g4 * 16 + rA, kb));
                ldsm4(bl, su + 65536 + swz(wn + g4 * 16 + rA, kb));
                #pragma unroll
                for (int mi = 0; mi < 3; mi++)
                    #pragma unroll
                    for (int o = 0; o < 2; o++) {
                        int ni = g4 * 2 + o;
                        mma_bf(acc[mi][ni], ah[mi], bh[o], bh[o + 2]);
                        mma_bf(acc[mi][ni], al[mi], bh[o], bh[o + 2]);
                        mma_bf(acc[mi][ni], ah[mi], bl[o], bl[o + 2]);
                    }
            }
        }

        #pragma unroll
        for (int mi = 0; mi < 3; mi++) {
            int mb = wm + mi * 16;
            int reg = mb >> 6;
            int o = (mb & 63) + (l >> 2);
            size_t base = (size_t)b * BELEM + (size_t)o * 32768 + (size_t)t * 512;
            #pragma unroll
            for (int ni = 0; ni < 4; ni++) {
                int col = n0 + wn + ni * 8 + 2 * (l & 3);
                float* d = acc[mi][ni];
                size_t o0 = base + col, o1 = o0 + (size_t)8 * 32768;
                if (reg == 0) {
                    float2 v0 = { d[0], d[1] }, v1 = { d[2], d[3] };
                    *(float2*)&g_U1[o0] = v0;
                    *(float2*)&g_U1[o1] = v1;
                } else if (reg == 1) {
                    store_hl(g_U2h, g_U2l, o0, d[0], d[1]);
                    store_hl(g_U2h, g_U2l, o1, d[2], d[3]);
                } else {
                    float2 v0 = { d[0], d[1] }, v1 = { d[2], d[3] };
                    *(float2*)&out[o0] = v0;
                    *(float2*)&out[o1] = v1;
                }
            }
        }
        __syncthreads();
    }
}

// ---------------------------------------------------------------------------
// k_gemm (512 thr): pass0: P = U1 + U2@La^T; pass1: out += P@La^T.
// CTA tile 128 x 256, K=512 in 8 chunks of 64, double-buffered cp.async.
// buffer (96KB): Ah 0, Al 16384, Bh 32768 (32K), Bl 65536 (32K); stride 98304
// warps: 16 = 4 m-warps (32 rows) x 4 n-warps (64 cols)
// ---------------------------------------------------------------------------
__device__ __forceinline__ void load_chunk(u32 sb, const u16* Ah, const u16* Al,
                                           const u16* Bh, const u16* Bl,
                                           int kc, int tid) {
    int k0 = kc * 64;
    #pragma unroll
    for (int it = 0; it < 12; it++) {
        int idx = it * 512 + tid;
        const u16* g;
        u32 s;
        if (idx < 2048) {                           // A tiles: 128 rows
            int half = idx >> 10;
            int r = (idx >> 3) & 127, c = idx & 7;
            g = (half ? Al : Ah) + (size_t)r * 512 + k0 + c * 8;
            s = sb + half * 16384 + swz(r, c * 16);
        } else {                                    // B tiles: 256 rows
            int rem = idx - 2048;
            int half = rem >> 11;
            int r = (rem >> 3) & 255, c = rem & 7;
            g = (half ? Bl : Bh) + (size_t)r * 512 + k0 + c * 8;
            s = sb + 32768 + half * 32768 + swz(r, c * 16);
        }
        cpa(s, g);
    }
    cpcommit();
}

__global__ __launch_bounds__(512, 1)
void k_gemm(float* __restrict__ out, int pass) {
    extern __shared__ char sm[];
    int tid = threadIdx.x, w = tid >> 5, l = tid & 31;
    int blk = blockIdx.x;
    int b = blk >> 6, mt = (blk >> 1) & 31, qt = blk & 1;
    int m0 = mt * 128, q0 = qt * 256;

    const u16* A0 = (pass ? g_Ph : g_U2h) + (size_t)b * BELEM + (size_t)m0 * 512;
    const u16* A1 = (pass ? g_Pl : g_U2l) + (size_t)b * BELEM + (size_t)m0 * 512;
    const u16* B0 = g_Lah + (size_t)b * LAELEM + (size_t)q0 * 512;
    const u16* B1 = g_Lal + (size_t)b * LAELEM + (size_t)q0 * 512;
    u32 su = s2u(sm);

    load_chunk(su, A0, A1, B0, B1, 0, tid);

    float acc[2][8][4];
    #pragma unroll
    for (int mi = 0; mi < 2; mi++)
        #pragma unroll
        for (int ni = 0; ni < 8; ni++)
            #pragma unroll
            for (int j = 0; j < 4; j++) acc[mi][ni][j] = 0.0f;

    int wm = (w >> 2) * 32, wn = (w & 3) * 64;
    int rA = ((l >> 3) & 1) * 8 + (l & 7);
    int ksel = ((l >> 4) & 1) * 16;

    for (int kc = 0; kc < 8; kc++) {
        if (kc < 7) {
            load_chunk(su + ((kc + 1) & 1) * 98304, A0, A1, B0, B1, kc + 1, tid);
            cpwait<1>();
        } else {
            cpwait<0>();
        }
        __syncthreads();
        u32 sb = su + (kc & 1) * 98304;
        #pragma unroll
        for (int s = 0; s < 4; s++) {
            int kb = s * 32 + ksel;
            u32 ah[2][4], al[2][4];
            #pragma unroll
            for (int mi = 0; mi < 2; mi++) {
                ldsm4(ah[mi], sb + swz(wm + mi * 16 + rA, kb));
                ldsm4(al[mi], sb + 16384 + swz(wm + mi * 16 + rA, kb));
            }
            #pragma unroll
            for (int g4 = 0; g4 < 4; g4++) {
                u32 bh[4], bl[4];
                ldsm4(bh, sb + 32768 + swz(wn + g4 * 16 + rA, kb));
                ldsm4(bl, sb + 65536 + swz(wn + g4 * 16 + rA, kb));
                #pragma unroll
                for (int mi = 0; mi < 2; mi++)
                    #pragma unroll
                    for (int o = 0; o < 2; o++) {
                        int ni = g4 * 2 + o;
                        mma_bf(acc[mi][ni], ah[mi], bh[o], bh[o + 2]);
                        mma_bf(acc[mi][ni], al[mi], bh[o], bh[o + 2]);
                        mma_bf(acc[mi][ni], ah[mi], bl[o], bl[o + 2]);
                    }
            }
        }
        __syncthreads();
    }

    #pragma unroll
    for (int mi = 0; mi < 2; mi++)
        #pragma unroll
        for (int ni = 0; ni < 8; ni++) {
            int row = m0 + wm + mi * 16 + (l >> 2);
            int col = q0 + wn + ni * 8 + 2 * (l & 3);
            size_t o0 = (size_t)b * BELEM + (size_t)row * 512 + col;
            size_t o1 = o0 + 8 * 512;
            float* d = acc[mi][ni];
            if (pass == 0) {
                float2 c0 = *(const float2*)&g_U1[o0];
                float2 c1 = *(const float2*)&g_U1[o1];
                store_hl(g_Ph, g_Pl, o0, d[0] + c0.x, d[1] + c0.y);
                store_hl(g_Ph, g_Pl, o1, d[2] + c1.x, d[3] + c1.y);
            } else {
                float2 c0 = *(const float2*)&out[o0];
                float2 c1 = *(const float2*)&out[o1];
                float2 v0 = { d[0] + c0.x, d[1] + c0.y };
                float2 v1 = { d[2] + c1.x, d[3] + c1.y };
                *(float2*)&out[o0] = v0;
                *(float2*)&out[o1] = v1;
            }
        }
}

// ---------------------------------------------------------------------------
extern "C" void kernel_launch(void* const* d_in, const int* in_sizes, int n_in,
                              void* d_out, int out_size) {
    const float* x  = (const float*)d_in[0];
    const float* La = (const float*)d_in[1];
    const float* W  = (const float*)d_in[2];
    float* out = (float*)d_out;
    (void)in_sizes; (void)n_in; (void)out_size;

    cudaFuncSetAttribute(k_mix,  cudaFuncAttributeMaxDynamicSharedMemorySize, 114688);
    cudaFuncSetAttribute(k_gemm, cudaFuncAttributeMaxDynamicSharedMemorySize, 196608);

    k_prep<<<4096, 256>>>(La);
    k_wstk<<<48, 256>>>(W);
    k_mix<<<1024, 512, 114688>>>(x, out);
    k_gemm<<<1024, 512, 196608>>>(out, 0);
    k_gemm<<<1024, 512, 196608>>>(out, 1);
}

// round 12
// speedup vs baseline: 2.7537x; 1.0820x over previous
#include <cuda_runtime.h>
#include <cuda_bf16.h>
#include <cstdint>

// Shapes: x[16,64,64,512], La[16,512,512], W[64,192]; out[16,64,64,512]
#define BELEM 2097152            // 64*64*512 per batch (row=o*64+t, col=n)
#define LAELEM 262144            // 512*512

typedef unsigned short u16;
typedef unsigned int u32;

__device__ __align__(16) float g_U1[(size_t)16 * BELEM];
__device__ __align__(16) u16   g_U2h[(size_t)16 * BELEM];
__device__ __align__(16) u16   g_U2l[(size_t)16 * BELEM];
__device__ __align__(16) u16   g_Ph [(size_t)16 * BELEM];
__device__ __align__(16) u16   g_Pl [(size_t)16 * BELEM];
__device__ __align__(16) u16   g_Lah[(size_t)16 * LAELEM];
__device__ __align__(16) u16   g_Lal[(size_t)16 * LAELEM];
__device__ __align__(16) u16   g_Wsh[192 * 64];
__device__ __align__(16) u16   g_Wsl[192 * 64];

// ---------------------------------------------------------------------------
__device__ __forceinline__ u32 s2u(const void* p) {
    u32 a;
    asm("{ .reg .u64 t; cvta.to.shared.u64 t, %1; cvt.u32.u64 %0, t; }" : "=r"(a) : "l"(p));
    return a;
}
__device__ __forceinline__ u32 swz(int row, int kb) {
    return (u32)(row * 128 + (kb ^ ((row & 7) << 4)));
}
__device__ __forceinline__ void cpa(u32 s, const void* g) {
    asm volatile("cp.async.cg.shared.global [%0], [%1], 16;" :: "r"(s), "l"(g));
}
__device__ __forceinline__ void cpcommit() {
    asm volatile("cp.async.commit_group;" ::: "memory");
}
template<int N> __device__ __forceinline__ void cpwait() {
    asm volatile("cp.async.wait_group %0;" :: "n"(N) : "memory");
}
__device__ __forceinline__ void ldsm4(u32* r, u32 a) {
    asm volatile("ldmatrix.sync.aligned.m8n8.x4.shared.b16 {%0,%1,%2,%3}, [%4];"
        : "=r"(r[0]), "=r"(r[1]), "=r"(r[2]), "=r"(r[3]) : "r"(a));
}
__device__ __forceinline__ void mma_bf(float* d, const u32* a, u32 b0, u32 b1) {
    asm volatile("mma.sync.aligned.m16n8k16.row.col.f32.bf16.bf16.f32 "
        "{%0,%1,%2,%3}, {%4,%5,%6,%7}, {%8,%9}, {%0,%1,%2,%3};"
        : "+f"(d[0]), "+f"(d[1]), "+f"(d[2]), "+f"(d[3])
        : "r"(a[0]), "r"(a[1]), "r"(a[2]), "r"(a[3]), "r"(b0), "r"(b1));
}
__device__ __forceinline__ u32 packlo(float lx, float ly) {
    u32 r;
    asm("cvt.rn.bf16x2.f32 %0, %1, %2;" : "=r"(r) : "f"(ly), "f"(lx));
    return r;
}
__device__ __forceinline__ void store_hl(u16* H, u16* L, size_t off, float v0, float v1) {
    u32 b0 = __float_as_uint(v0), b1 = __float_as_uint(v1);
    *(u32*)(H + off) = __byte_perm(b0, b1, 0x7632);
    float r0 = v0 - __uint_as_float(b0 & 0xFFFF0000u);
    float r1 = v1 - __uint_as_float(b1 & 0xFFFF0000u);
    *(u32*)(L + off) = packlo(r0, r1);
}

// ---------------------------------------------------------------------------
__global__ void k_prep(const float* __restrict__ La) {
    int i = blockIdx.x * blockDim.x + threadIdx.x;
    float4 v = __ldg((const float4*)La + i);
    u32 bx = __float_as_uint(v.x), by = __float_as_uint(v.y);
    u32 bz = __float_as_uint(v.z), bw = __float_as_uint(v.w);
    uint2 h = { __byte_perm(bx, by, 0x7632), __byte_perm(bz, bw, 0x7632) };
    uint2 l = { packlo(v.x - __uint_as_float(bx & 0xFFFF0000u),
                       v.y - __uint_as_float(by & 0xFFFF0000u)),
                packlo(v.z - __uint_as_float(bz & 0xFFFF0000u),
                       v.w - __uint_as_float(bw & 0xFFFF0000u)) };
    ((uint2*)g_Lah)[i] = h;
    ((uint2*)g_Lal)[i] = l;
}

__global__ void k_wstk(const float* __restrict__ W) {
    int i = blockIdx.x * blockDim.x + threadIdx.x;
    if (i >= 192 * 64) return;
    int r = i >> 6, c = i & 63;
    int o = r & 63, reg = r >> 6;
    float v = (reg == 0) ? W[o * 192 + 3 * c + 1]
            : (reg == 1) ? 2.0f * W[o * 192 + 3 * c + 2]
            : W[o * 192 + 3 * c] - W[o * 192 + 3 * c + 2];
    u32 u = __float_as_uint(v);
    g_Wsh[i] = (u16)(u >> 16);
    float res = v - __uint_as_float(u & 0xFFFF0000u);
    __nv_bfloat16 rb = __float2bfloat16(res);
    g_Wsl[i] = *(u16*)&rb;
}

// ---------------------------------------------------------------------------
// k_mix (512 thr, double-buffered staging): per (b,t):
// A=Wstk[192][64] h/l, B=X^T [128 n][64 c] h/l.
// Rows 0-63 -> U1 fp32, 64-127 -> U2 h/l, 128-191 -> out fp32.
// smem: Wh 0 (24K), Wl 24576; buf k (k=0,1) at 49152+k*65536:
//       Bh +0 (16K), Bl +16384, stage +32768 (32K fp32). total 180224
// ---------------------------------------------------------------------------
__global__ __launch_bounds__(512, 1)
void k_mix(const float* __restrict__ x, float* __restrict__ out) {
    extern __shared__ char sm[];
    int tid = threadIdx.x, w = tid >> 5, l = tid & 31;
    int b = blockIdx.x >> 6, t = blockIdx.x & 63;
    u32 su = s2u(sm);
    const float* xb = x + (size_t)b * BELEM + (size_t)t * 512;

    #pragma unroll
    for (int it = 0; it < 6; it++) {               // W: 3072 16B chunks
        int idx = it * 512 + tid;
        int half = idx >= 1536;
        int rem = idx - half * 1536;
        int r = rem >> 3, c = rem & 7;
        const u16* g = (half ? g_Wsl : g_Wsh) + r * 64 + c * 8;
        cpa(su + half * 24576 + swz(r, c * 16), g);
    }
    cpcommit();

    // prologue: stage chunk 0
    #pragma unroll
    for (int it = 0; it < 4; it++) {
        int idx = it * 512 + tid;
        int c = idx >> 5, q = idx & 31;
        cpa(su + 49152 + 32768 + (u32)(c * 512 + q * 16), xb + (size_t)c * 32768 + q * 4);
    }
    cpcommit();

    int wm = (w >> 2) * 48, wn = (w & 3) * 32;
    int rA = ((l >> 3) & 1) * 8 + (l & 7);
    int ksel = ((l >> 4) & 1) * 16;

    for (int nc = 0; nc < 4; nc++) {
        u32 bo = su + 49152 + (u32)(nc & 1) * 65536;          // this chunk's buf
        if (nc < 3) {
            u32 bn = su + 49152 + (u32)((nc + 1) & 1) * 65536;
            int n1 = (nc + 1) * 128;
            #pragma unroll
            for (int it = 0; it < 4; it++) {
                int idx = it * 512 + tid;
                int c = idx >> 5, q = idx & 31;
                cpa(bn + 32768 + (u32)(c * 512 + q * 16),
                    xb + (size_t)c * 32768 + n1 + q * 4);
            }
            cpcommit();
            cpwait<1>();
        } else {
            cpwait<0>();
        }
        __syncthreads();
        float* stage = (float*)(sm + (bo - su) + 32768);
        #pragma unroll
        for (int it = 0; it < 8; it++) {           // transpose+convert -> B [n][c]
            int idx = it * 512 + tid;
            int cp2 = idx >> 7, n = idx & 127;
            float a0 = stage[(cp2 * 2) * 128 + n];
            float a1 = stage[(cp2 * 2 + 1) * 128 + n];
            u32 u0 = __float_as_uint(a0), u1 = __float_as_uint(a1);
            u32 off = swz(n, cp2 * 4);
            *(u32*)(sm + (bo - su) + off) = __byte_perm(u0, u1, 0x7632);
            *(u32*)(sm + (bo - su) + 16384 + off) =
                packlo(a0 - __uint_as_float(u0 & 0xFFFF0000u),
                       a1 - __uint_as_float(u1 & 0xFFFF0000u));
        }
        __syncthreads();

        float acc[3][4][4];
        #pragma unroll
        for (int mi = 0; mi < 3; mi++)
            #pragma unroll
            for (int ni = 0; ni < 4; ni++)
                #pragma unroll
                for (int j = 0; j < 4; j++) acc[mi][ni][j] = 0.0f;

        #pragma unroll
        for (int s = 0; s < 4; s++) {
            int kb = s * 32 + ksel;
            u32 ah[3][4], al[3][4];
            #pragma unroll
            for (int mi = 0; mi < 3; mi++) {
                ldsm4(ah[mi], su + swz(wm + mi * 16 + rA, kb));
                ldsm4(al[mi], su + 24576 + swz(wm + mi * 16 + rA, kb));
            }
            #pragma unroll
            for (int g4 = 0; g4 < 2; g4++) {
                u32 bh[4], bl[4];
                ldsm4(bh, bo + swz(wn + g4 * 16 + rA, kb));
                ldsm4(bl, bo + 16384 + swz(wn + g4 * 16 + rA, kb));
                #pragma unroll
                for (int mi = 0; mi < 3; mi++)
                    #pragma unroll
                    for (int o = 0; o < 2; o++) {
                        int ni = g4 * 2 + o;
                        mma_bf(acc[mi][ni], ah[mi], bh[o], bh[o + 2]);
                        mma_bf(acc[mi][ni], al[mi], bh[o], bh[o + 2]);
                        mma_bf(acc[mi][ni], ah[mi], bl[o], bl[o + 2]);
                    }
            }
        }

        int n0 = nc * 128;
        #pragma unroll
        for (int mi = 0; mi < 3; mi++) {
            int mb = wm + mi * 16;
            int reg = mb >> 6;
            int o = (mb & 63) + (l >> 2);
            size_t base = (size_t)b * BELEM + (size_t)o * 32768 + (size_t)t * 512;
            #pragma unroll
            for (int ni = 0; ni < 4; ni++) {
                int col = n0 + wn + ni * 8 + 2 * (l & 3);
                float* d = acc[mi][ni];
                size_t o0 = base + col, o1 = o0 + (size_t)8 * 32768;
                if (reg == 0) {
                    float2 v0 = { d[0], d[1] }, v1 = { d[2], d[3] };
                    *(float2*)&g_U1[o0] = v0;
                    *(float2*)&g_U1[o1] = v1;
                } else if (reg == 1) {
                    store_hl(g_U2h, g_U2l, o0, d[0], d[1]);
                    store_hl(g_U2h, g_U2l, o1, d[2], d[3]);
                } else {
                    float2 v0 = { d[0], d[1] }, v1 = { d[2], d[3] };
                    *(float2*)&out[o0] = v0;
                    *(float2*)&out[o1] = v1;
                }
            }
        }
    }
}

// ---------------------------------------------------------------------------
// k_gemm (256 thr, 2 CTAs/SM, 3-stage): pass0: P = U1 + U2@La^T;
// pass1: out += P@La^T.  CTA tile 128x128, K=512 in 16 chunks of 32.
// Stage (32KB): A tile 16KB (row: bytes 0-63 hi k32, 64-127 lo k32), B tile
// 16KB same packing, at +16384. 3 stages (96KB).
// warps: 8 = 2 m-warps (64 rows) x 4 n-warps (32 cols)
// ---------------------------------------------------------------------------
__device__ __forceinline__ void load_chunk(u32 sb, const u16* Ah, const u16* Al,
                                           const u16* Bh, const u16* Bl,
                                           int kc, int tid) {
    int k0 = kc * 32;
    #pragma unroll
    for (int it = 0; it < 8; it++) {
        int idx = it * 256 + tid;
        int tile = idx >> 10;                        // 0=A, 1=B
        int r = (idx >> 3) & 127, c = idx & 7;
        int lo = c >> 2;
        const u16* base = tile ? (lo ? Bl : Bh) : (lo ? Al : Ah);
        const u16* g = base + (size_t)r * 512 + k0 + (c & 3) * 8;
        cpa(sb + tile * 16384 + swz(r, c * 16), g);
    }
    cpcommit();
}

__global__ __launch_bounds__(256, 2)
void k_gemm(float* __restrict__ out, int pass) {
    extern __shared__ char sm[];
    int tid = threadIdx.x, w = tid >> 5, l = tid & 31;
    int blk = blockIdx.x;
    int b = blk >> 7, mt = (blk >> 2) & 31, qt = blk & 3;
    int m0 = mt * 128, q0 = qt * 128;

    const u16* A0 = (pass ? g_Ph : g_U2h) + (size_t)b * BELEM + (size_t)m0 * 512;
    const u16* A1 = (pass ? g_Pl : g_U2l) + (size_t)b * BELEM + (size_t)m0 * 512;
    const u16* B0 = g_Lah + (size_t)b * LAELEM + (size_t)q0 * 512;
    const u16* B1 = g_Lal + (size_t)b * LAELEM + (size_t)q0 * 512;
    u32 su = s2u(sm);

    load_chunk(su,         A0, A1, B0, B1, 0, tid);
    load_chunk(su + 32768, A0, A1, B0, B1, 1, tid);

    float acc[4][4][4];
    #pragma unroll
    for (int mi = 0; mi < 4; mi++)
        #pragma unroll
        for (int ni = 0; ni < 4; ni++)
            #pragma unroll
            for (int j = 0; j < 4; j++) acc[mi][ni][j] = 0.0f;

    int wm = (w >> 2) * 64, wn = (w & 3) * 32;
    int rA = ((l >> 3) & 1) * 8 + (l & 7);
    int ksel = ((l >> 4) & 1) * 16;

    for (int kc = 0; kc < 16; kc++) {
        if (kc < 14) cpwait<1>(); else cpwait<0>();
        __syncthreads();
        if (kc + 2 < 16)
            load_chunk(su + (u32)((kc + 2) % 3) * 32768, A0, A1, B0, B1, kc + 2, tid);
        u32 sb = su + (u32)(kc % 3) * 32768;
        #pragma unroll
        for (int s = 0; s < 2; s++) {
            int kb = s * 32 + ksel;
            u32 ah[4][4], al[4][4];
            #pragma unroll
            for (int mi = 0; mi < 4; mi++) {
                ldsm4(ah[mi], sb + swz(wm + mi * 16 + rA, kb));
                ldsm4(al[mi], sb + swz(wm + mi * 16 + rA, kb + 64));
            }
            #pragma unroll
            for (int g4 = 0; g4 < 2; g4++) {
                u32 bh[4], bl[4];
                ldsm4(bh, sb + 16384 + swz(wn + g4 * 16 + rA, kb));
                ldsm4(bl, sb + 16384 + swz(wn + g4 * 16 + rA, kb + 64));
                #pragma unroll
                for (int mi = 0; mi < 4; mi++)
                    #pragma unroll
                    for (int o = 0; o < 2; o++) {
                        int ni = g4 * 2 + o;
                        mma_bf(acc[mi][ni], ah[mi], bh[o], bh[o + 2]);
                        mma_bf(acc[mi][ni], al[mi], bh[o], bh[o + 2]);
                        mma_bf(acc[mi][ni], ah[mi], bl[o], bl[o + 2]);
                    }
            }
        }
    }

    #pragma unroll
    for (int mi = 0; mi < 4; mi++)
        #pragma unroll
        for (int ni = 0; ni < 4; ni++) {
            int row = m0 + wm + mi * 16 + (l >> 2);
            int col = q0 + wn + ni * 8 + 2 * (l & 3);
            size_t o0 = (size_t)b * BELEM + (size_t)row * 512 + col;
            size_t o1 = o0 + 8 * 512;
            float* d = acc[mi][ni];
            if (pass == 0) {
                float2 c0 = *(const float2*)&g_U1[o0];
                float2 c1 = *(const float2*)&g_U1[o1];
                store_hl(g_Ph, g_Pl, o0, d[0] + c0.x, d[1] + c0.y);
                store_hl(g_Ph, g_Pl, o1, d[2] + c1.x, d[3] + c1.y);
            } else {
                float2 c0 = *(const float2*)&out[o0];
                float2 c1 = *(const float2*)&out[o1];
                float2 v0 = { d[0] + c0.x, d[1] + c0.y };
                float2 v1 = { d[2] + c1.x, d[3] + c1.y };
                *(float2*)&out[o0] = v0;
                *(float2*)&out[o1] = v1;
            }
        }
}

// ---------------------------------------------------------------------------
extern "C" void kernel_launch(void* const* d_in, const int* in_sizes, int n_in,
                              void* d_out, int out_size) {
    const float* x  = (const float*)d_in[0];
    const float* La = (const float*)d_in[1];
    const float* W  = (const float*)d_in[2];
    float* out = (float*)d_out;
    (void)in_sizes; (void)n_in; (void)out_size;

    cudaFuncSetAttribute(k_mix,  cudaFuncAttributeMaxDynamicSharedMemorySize, 180224);
    cudaFuncSetAttribute(k_gemm, cudaFuncAttributeMaxDynamicSharedMemorySize, 98304);

    k_prep<<<4096, 256>>>(La);
    k_wstk<<<48, 256>>>(W);
    k_mix<<<1024, 512, 180224>>>(x, out);
    k_gemm<<<2048, 256, 98304>>>(out, 0);
    k_gemm<<<2048, 256, 98304>>>(out, 1);
}